// round 13
// baseline (speedup 1.0000x reference)
#include <cuda_runtime.h>
#include <cuda_bf16.h>
#include <cstdint>

typedef unsigned long long ull;

#define B_    64
#define T_    2048
#define H_    512
#define G_    2048      // 4*H
#define NCTA  256       // 4 groups x 64 CTAs, 2 CTAs per SM
#define GCTA  64        // CTAs per group
#define GB    16        // batches per group
#define LC    32        // gate cols per CTA (8 hcols x 4 gates)

// ---------------- device scratch (static, allowed) ----------------
__device__ __align__(16) float  g_hs[(size_t)T_ * H_ * B_];        // 256 MB [t][k][b] natural
__device__ __align__(16) float  g_whP[GCTA * H_ * LC];             // 4 MB [ci][k][lc]
__device__ __align__(16) float  g_bossT4[50 * H_ * 4];             // [v][hcol][gate]
__device__ __align__(16) float  g_heroT4[200 * H_ * 4];            // [v][hcol][gate]
__device__ __align__(16) float4 g_cwb[G_];                         // (Wc0,Wc1,Wc2,bias) by o
__device__ __align__(16) float  g_hbufG[4 * 2 * H_ * GB];          // per-group double-buffered h
__device__ unsigned g_barG[4 * 32];                                // per-group counters, 128B apart

// ---------------- helpers ----------------
__device__ __forceinline__ ull pk2(float x, float y) {
    ull r; asm("mov.b64 %0, {%1,%2};" : "=l"(r) : "f"(x), "f"(y)); return r;
}
__device__ __forceinline__ float2 upk(ull v) {
    float2 f; asm("mov.b64 {%0,%1}, %2;" : "=f"(f.x), "=f"(f.y) : "l"(v)); return f;
}
__device__ __forceinline__ void fma2(ull& d, ull a, ull b) {
    asm("fma.rn.f32x2 %0, %1, %2, %3;" : "=l"(d) : "l"(a), "l"(b), "l"(d));
}
__device__ __forceinline__ void cp16(uint32_t s, const void* g) {
    asm volatile("cp.async.cg.shared.global [%0], [%1], 16;" :: "r"(s), "l"(g) : "memory");
}
__device__ __forceinline__ void cpcommit() { asm volatile("cp.async.commit_group;" ::: "memory"); }
template <int N> __device__ __forceinline__ void cpwait() {
    asm volatile("cp.async.wait_group %0;" :: "n"(N) : "memory");
}
__device__ __forceinline__ float sigf(float x) { return 1.0f / (1.0f + __expf(-x)); }
__device__ __forceinline__ float tanha(float x) {
    float r; asm("tanh.approx.f32 %0, %1;" : "=f"(r) : "f"(x)); return r;
}

// ---------------- kernel 0: init ----------------
__global__ void k_init() {
    int tid = threadIdx.x + blockIdx.x * blockDim.x;
    if (tid < 4 * 32) g_barG[tid] = 0u;
    for (int i = tid; i < 4 * 2 * H_ * GB; i += blockDim.x * gridDim.x)
        g_hbufG[i] = 0.f;
}

// ---------------- kernel 1: projections (gate-packed tables) ----------------
__global__ void k_prep(const float* __restrict__ boss_table,
                       const float* __restrict__ hero_table,
                       const float* __restrict__ W_i,
                       const float* __restrict__ b_lstm) {
    int o = blockIdx.x;
    int gate = o >> 9, hcol = o & 511;
    int tid = threadIdx.x;
    if (tid < 50) {
        float s = 0.f;
        #pragma unroll
        for (int e = 0; e < 32; ++e) s += boss_table[tid * 32 + e] * W_i[e * G_ + o];
        g_bossT4[(tid * H_ + hcol) * 4 + gate] = s;
    } else if (tid < 250) {
        int v = tid - 50;
        float s = 0.f;
        #pragma unroll
        for (int e = 0; e < 32; ++e) s += hero_table[v * 32 + e] * W_i[(32 + e) * G_ + o];
        g_heroT4[(v * H_ + hcol) * 4 + gate] = s;
    } else if (tid == 250) {
        g_cwb[o] = make_float4(W_i[64 * G_ + o], W_i[65 * G_ + o], W_i[66 * G_ + o], b_lstm[o]);
    }
}

// ---------------- kernel 1b: W_h permute -> whP[ci][k][lc] ----------------
// grid = 1024 blocks: (ci in 64) x (kb in 16); 256 threads: 32 k x 8 lc-quads
__global__ void k_prepW(const float* __restrict__ W_h) {
    int ci = blockIdx.x >> 4, kb = blockIdx.x & 15;
    int tid = threadIdx.x;
    int k = kb * 32 + (tid >> 3);
    int lc0 = (tid & 7) * 4;
    #pragma unroll
    for (int l = 0; l < 4; ++l) {
        int lc = lc0 + l;
        int gate = lc >> 3, jj = lc & 7;
        int o = gate * H_ + ci * 8 + jj;
        g_whP[((size_t)ci * H_ + k) * LC + lc] = W_h[(size_t)k * G_ + o];
    }
}

// ---------------- kernel 3: persistent LSTM recurrence (2 CTAs/SM) ----------------
// grid = 256 (4 groups x 64), block = 256 (8 warps, ksplit-8), occupancy 2
// smem: W 64KB + h/partials 32KB (aliased) + stage 1KB = 99KB
#define SM_W    0
#define SM_H    65536
#define SM_STG  (65536 + 32768)
#define SMTOT   (SM_STG + 1024)
__global__ void __launch_bounds__(256, 2) k_recur(const int* __restrict__ boss_anim,
                                                  const int* __restrict__ hero_anim,
                                                  const float* __restrict__ cont) {
    extern __shared__ char smem[];
    char* whsB = smem + SM_W;           // [512 k][128B] = 32 lc f32 per row
    char* hsmB = smem + SM_H;           // [512 k][64B] h ; aliased per-warp partials
    int*   ibuf = (int*)(smem + SM_STG);           // [2][16][2]
    float* cbuf = (float*)(smem + SM_STG + 256);   // [2][16][4]

    int cta = blockIdx.x, tid = threadIdx.x;
    int w = tid >> 5, lane = tid & 31;
    int cg = lane & 7, bg = lane >> 3;  // 8 col-groups (4 lc each) x 4 batch-groups
    int gp = cta & 3, ci = cta >> 2;    // interleave groups across adjacent bids

    // one-time: stage W slice (64KB)
    {
        const float4* wsrc = (const float4*)(g_whP + (size_t)ci * H_ * LC);
        float4* wdst = (float4*)whsB;
        for (int i = tid; i < H_ * LC / 4; i += 256) wdst[i] = wsrc[i];
    }

    // gate roles: threads 0..127 = (j in 8 hcols, b2 in 16 batches)
    bool gact = (tid < 128);
    int j = tid >> 4, b2 = tid & 15;    // j in 0..7 for active threads
    int hcol = ci * 8 + j;
    float c_state = 0.f;

    // preload cont-weights+bias for this thread's 4 gate cols
    float4 cw[4];
    if (gact) {
        #pragma unroll
        for (int g = 0; g < 4; ++g) cw[g] = g_cwb[g * H_ + hcol];
    }

    uint32_t hsm_s = (uint32_t)__cvta_generic_to_shared(hsmB);
    float* hbuf0 = g_hbufG + (size_t)gp * 2 * H_ * GB;
    unsigned* bar = g_barG + gp * 32;

    // ---- prologue: stage slot 0 + compute xg(t=0) ----
    if (w == 0) {
        if (lane < 16) {
            int b = gp * GB + lane;
            int bi = boss_anim[b * T_ + 0]; bi = min(max(bi, 0), 49);
            ibuf[(0 * 16 + lane) * 2 + 0] = bi;
            size_t cb = (size_t)b * T_ * 3;
            cbuf[(0 * 16 + lane) * 4 + 0] = cont[cb + 0];
            cbuf[(0 * 16 + lane) * 4 + 1] = cont[cb + 1];
            cbuf[(0 * 16 + lane) * 4 + 2] = cont[cb + 2];
        } else {
            int bb = lane - 16;
            int b = gp * GB + bb;
            int hi = hero_anim[b * T_ + 0]; hi = min(max(hi, 0), 199);
            ibuf[(0 * 16 + bb) * 2 + 1] = hi;
        }
    }
    __syncthreads();

    float xcur[4] = {0.f, 0.f, 0.f, 0.f};
    if (gact) {
        int bi = ibuf[(0 * 16 + b2) * 2 + 0];
        int hi = ibuf[(0 * 16 + b2) * 2 + 1];
        float c0 = cbuf[(0 * 16 + b2) * 4 + 0];
        float c1 = cbuf[(0 * 16 + b2) * 4 + 1];
        float c2 = cbuf[(0 * 16 + b2) * 4 + 2];
        float4 bv4 = *(const float4*)(g_bossT4 + ((size_t)bi * H_ + hcol) * 4);
        float4 hv4 = *(const float4*)(g_heroT4 + ((size_t)hi * H_ + hcol) * 4);
        xcur[0] = bv4.x + hv4.x + c0 * cw[0].x + c1 * cw[0].y + c2 * cw[0].z + cw[0].w;
        xcur[1] = bv4.y + hv4.y + c0 * cw[1].x + c1 * cw[1].y + c2 * cw[1].z + cw[1].w;
        xcur[2] = bv4.z + hv4.z + c0 * cw[2].x + c1 * cw[2].y + c2 * cw[2].z + cw[2].w;
        xcur[3] = bv4.w + hv4.w + c0 * cw[3].x + c1 * cw[3].y + c2 * cw[3].z + cw[3].w;
    }

    for (int t = 0; t < T_; ++t) {
        int tp = min(t + 1, T_ - 1);
        int nb = (t + 1) & 1;

        // -------- async-load own 4KB k-slice FIRST (4 groups of 2 cp16) --------
        const char* src = (const char*)(hbuf0 + (size_t)(t & 1) * H_ * GB) + w * 4096;
        uint32_t dst = hsm_s + w * 4096;
        #pragma unroll
        for (int g = 0; g < 4; ++g) {
            cp16(dst + (g * 2 + 0) * 512 + lane * 16, src + (g * 2 + 0) * 512 + lane * 16);
            cp16(dst + (g * 2 + 1) * 512 + lane * 16, src + (g * 2 + 1) * 512 + lane * 16);
            cpcommit();
        }

        // -------- warp0: issue stage loads for t+1 (into regs) --------
        int sbi = 0, shi = 0; float sc0 = 0, sc1 = 0, sc2 = 0;
        if (w == 0) {
            if (lane < 16) {
                int b = gp * GB + lane;
                sbi = boss_anim[b * T_ + tp];
                size_t cb = ((size_t)b * T_ + tp) * 3;
                sc0 = cont[cb + 0]; sc1 = cont[cb + 1]; sc2 = cont[cb + 2];
            } else {
                int b = gp * GB + (lane - 16);
                shi = hero_anim[b * T_ + tp];
            }
        }

        ull acc[8];
        #pragma unroll
        for (int a = 0; a < 8; ++a) acc[a] = 0ull;

        const char* wP = whsB + (w * 64) * 128 + cg * 16;
        const char* hP = hsmB + (w * 64) * 64 + bg * 16;

        #define GBODY                                                          \
        {                                                                      \
            float4 hv = *(const float4*)(hP);                                  \
            ulonglong2 wA = *(const ulonglong2*)(wP);                          \
            ull h0 = pk2(hv.x, hv.x), h1 = pk2(hv.y, hv.y);                    \
            ull h2 = pk2(hv.z, hv.z), h3 = pk2(hv.w, hv.w);                    \
            fma2(acc[0], wA.x, h0); fma2(acc[1], wA.y, h0);                    \
            fma2(acc[2], wA.x, h1); fma2(acc[3], wA.y, h1);                    \
            fma2(acc[4], wA.x, h2); fma2(acc[5], wA.y, h2);                    \
            fma2(acc[6], wA.x, h3); fma2(acc[7], wA.y, h3);                    \
            wP += 128; hP += 64;                                               \
        }

        // -------- GEMM: 4 chunks of 16 k, each gated by its cp group --------
        cpwait<3>();
        __syncwarp();
        #pragma unroll 8
        for (int k = 0; k < 16; ++k) GBODY
        cpwait<2>();
        __syncwarp();
        #pragma unroll 8
        for (int k = 0; k < 16; ++k) GBODY
        cpwait<1>();
        __syncwarp();
        #pragma unroll 8
        for (int k = 0; k < 16; ++k) GBODY
        cpwait<0>();
        __syncwarp();
        #pragma unroll 8
        for (int k = 0; k < 16; ++k) GBODY
        #undef GBODY

        // -------- warp0: commit stage to smem (before the block sync) --------
        if (w == 0) {
            if (lane < 16) {
                int bi = min(max(sbi, 0), 49);
                ibuf[(nb * 16 + lane) * 2 + 0] = bi;
                cbuf[(nb * 16 + lane) * 4 + 0] = sc0;
                cbuf[(nb * 16 + lane) * 4 + 1] = sc1;
                cbuf[(nb * 16 + lane) * 4 + 2] = sc2;
            } else {
                int hi = min(max(shi, 0), 199);
                ibuf[(nb * 16 + (lane - 16)) * 2 + 1] = hi;
            }
        }

        // -------- store partials into OWN slice (done reading it) --------
        // layout per warp: [16 b2 rows of 144B][32 lc floats + pad]
        #pragma unroll
        for (int b = 0; b < 4; ++b) {
            char* pb = hsmB + w * 4096 + (bg * 4 + b) * 144 + cg * 16;
            *(ulonglong2*)(pb) = make_ulonglong2(acc[2 * b], acc[2 * b + 1]);
        }
        __syncthreads();

        float h = 0.f;   // lives in a register across the barrier
        if (gact) {
            // -------- issue gather LDGs for xg(t+1) --------
            int nbi = ibuf[(nb * 16 + b2) * 2 + 0];
            int nhi = ibuf[(nb * 16 + b2) * 2 + 1];
            float nc0 = cbuf[(nb * 16 + b2) * 4 + 0];
            float nc1 = cbuf[(nb * 16 + b2) * 4 + 1];
            float nc2 = cbuf[(nb * 16 + b2) * 4 + 2];
            float4 bv4 = *(const float4*)(g_bossT4 + ((size_t)nbi * H_ + hcol) * 4);
            float4 hv4 = *(const float4*)(g_heroT4 + ((size_t)nhi * H_ + hcol) * 4);

            // -------- fused ksplit reduction + gates (uses xcur) --------
            float gs[4];
            #pragma unroll
            for (int g0 = 0; g0 < 4; ++g0) {
                int lc = g0 * 8 + j;
                float s = 0.f;
                #pragma unroll
                for (int w8 = 0; w8 < 8; ++w8)
                    s += *(const float*)(hsmB + w8 * 4096 + b2 * 144 + lc * 4);
                gs[g0] = s;
            }
            float gi = gs[0] + xcur[0], gf = gs[1] + xcur[1];
            float gg = gs[2] + xcur[2], go = gs[3] + xcur[3];
            float iv = sigf(gi), fv = sigf(gf), gv = tanha(gg), ov = sigf(go);
            c_state = fv * c_state + iv * gv;
            h = ov * tanha(c_state);
            hbuf0[(size_t)nb * H_ * GB + hcol * GB + b2] = h;

            // -------- compute xg(t+1) --------
            xcur[0] = bv4.x + hv4.x + nc0 * cw[0].x + nc1 * cw[0].y + nc2 * cw[0].z + cw[0].w;
            xcur[1] = bv4.y + hv4.y + nc0 * cw[1].x + nc1 * cw[1].y + nc2 * cw[1].z + cw[1].w;
            xcur[2] = bv4.z + hv4.z + nc0 * cw[2].x + nc1 * cw[2].y + nc2 * cw[2].z + cw[2].w;
            xcur[3] = bv4.w + hv4.w + nc0 * cw[3].x + nc1 * cw[3].y + nc2 * cw[3].z + cw[3].w;
        }

        // -------- group barrier (frozen R7 form), archive store from REGISTER
        //          overlapped into the spin window --------
        __threadfence();
        __syncthreads();
        if (gact) {
            g_hs[((size_t)t * H_ + hcol) * B_ + gp * GB + b2] = h;
        }
        if (tid == 0) {
            atomicAdd(bar, 1u);
            unsigned tgt = (unsigned)GCTA * (unsigned)(t + 1);
            while (*(volatile unsigned*)bar < tgt) { }
            __threadfence();
        }
        __syncthreads();
    }
}

// ---------------- kernel 4: MLP epilogue ----------------
__global__ void __launch_bounds__(256, 1) k_mlp(const float* __restrict__ W1,
                                                const float* __restrict__ b1,
                                                const float* __restrict__ W2,
                                                const float* __restrict__ b2,
                                                float* __restrict__ out) {
    extern __shared__ char smem[];
    float* hsm = (float*)smem;                          // [512][64] 128KB
    float* w1c = (float*)(smem + 131072);               // [64][256] 64KB
    float* b1s = (float*)(smem + 131072 + 65536);       // 256
    float* w2s = b1s + 256;                             // 256
    float* red = w2s + 256;                             // [16][64]

    int t = blockIdx.x, tid = threadIdx.x;

    const float4* hsrc = (const float4*)(g_hs + (size_t)t * (H_ * B_));
    float4* hd = (float4*)hsm;
    for (int i = tid; i < H_ * B_ / 4; i += 256) hd[i] = hsrc[i];
    b1s[tid] = b1[tid];
    w2s[tid] = W2[tid];
    __syncthreads();

    int bt = tid & 15, mt = tid >> 4;
    int b0 = bt * 4, m0 = mt * 16;

    ull acc[16][2];
    #pragma unroll
    for (int m = 0; m < 16; ++m) {
        float bv = b1s[m0 + m];
        acc[m][0] = pk2(bv, bv);
        acc[m][1] = pk2(bv, bv);
    }

    for (int kc = 0; kc < 8; ++kc) {
        if (kc > 0) __syncthreads();
        const float4* wsrc = (const float4*)(W1 + (size_t)kc * 64 * 256);
        for (int i = tid; i < 4096; i += 256) ((float4*)w1c)[i] = wsrc[i];
        __syncthreads();
        #pragma unroll 4
        for (int k = 0; k < 64; ++k) {
            const ull* hp = (const ull*)&hsm[(kc * 64 + k) * B_ + b0];
            ull h01 = hp[0], h23 = hp[1];
            const float* wr = &w1c[k * 256 + m0];
            #pragma unroll
            for (int m4 = 0; m4 < 4; ++m4) {
                float4 wv = *(const float4*)&wr[m4 * 4];
                ull wa = pk2(wv.x, wv.x), wb = pk2(wv.y, wv.y);
                ull wc = pk2(wv.z, wv.z), wd = pk2(wv.w, wv.w);
                fma2(acc[m4 * 4 + 0][0], h01, wa); fma2(acc[m4 * 4 + 0][1], h23, wa);
                fma2(acc[m4 * 4 + 1][0], h01, wb); fma2(acc[m4 * 4 + 1][1], h23, wb);
                fma2(acc[m4 * 4 + 2][0], h01, wc); fma2(acc[m4 * 4 + 2][1], h23, wc);
                fma2(acc[m4 * 4 + 3][0], h01, wd); fma2(acc[m4 * 4 + 3][1], h23, wd);
            }
        }
    }

    float p0 = 0.f, p1 = 0.f, p2 = 0.f, p3 = 0.f;
    #pragma unroll
    for (int m = 0; m < 16; ++m) {
        float2 v0 = upk(acc[m][0]), v1 = upk(acc[m][1]);
        float wv = w2s[m0 + m];
        p0 += fmaxf(v0.x, 0.f) * wv;
        p1 += fmaxf(v0.y, 0.f) * wv;
        p2 += fmaxf(v1.x, 0.f) * wv;
        p3 += fmaxf(v1.y, 0.f) * wv;
    }
    red[mt * B_ + b0 + 0] = p0;
    red[mt * B_ + b0 + 1] = p1;
    red[mt * B_ + b0 + 2] = p2;
    red[mt * B_ + b0 + 3] = p3;
    __syncthreads();
    if (tid < B_) {
        float s = b2[0];
        #pragma unroll
        for (int q = 0; q < 16; ++q) s += red[q * B_ + tid];
        out[(size_t)tid * T_ + t] = s;
    }
}

// ---------------- launch ----------------
extern "C" void kernel_launch(void* const* d_in, const int* in_sizes, int n_in,
                              void* d_out, int out_size) {
    const int*   boss_anim  = (const int*)d_in[0];
    const int*   hero_anim  = (const int*)d_in[1];
    const float* continuous = (const float*)d_in[2];
    const float* boss_table = (const float*)d_in[3];
    const float* hero_table = (const float*)d_in[4];
    const float* W_i        = (const float*)d_in[5];
    const float* W_h        = (const float*)d_in[6];
    const float* b_lstm     = (const float*)d_in[7];
    const float* W1         = (const float*)d_in[8];
    const float* b1         = (const float*)d_in[9];
    const float* W2         = (const float*)d_in[10];
    const float* b2         = (const float*)d_in[11];
    float* out = (float*)d_out;

    static bool attr_done = false;
    if (!attr_done) {
        cudaFuncSetAttribute(k_recur, cudaFuncAttributeMaxDynamicSharedMemorySize, SMTOT);
        cudaFuncSetAttribute(k_mlp,   cudaFuncAttributeMaxDynamicSharedMemorySize, 131072 + 65536 + 2048 + 4096);
        attr_done = true;
    }

    k_init<<<32, 256>>>();
    k_prep<<<G_, 256>>>(boss_table, hero_table, W_i, b_lstm);
    k_prepW<<<1024, 256>>>(W_h);
    k_recur<<<NCTA, 256, SMTOT>>>(boss_anim, hero_anim, continuous);
    k_mlp<<<T_, 256, 131072 + 65536 + 2048 + 4096>>>(W1, b1, W2, b2, out);
}

// round 14
// speedup vs baseline: 1.1015x; 1.1015x over previous
#include <cuda_runtime.h>
#include <cuda_bf16.h>
#include <cstdint>

typedef unsigned long long ull;

#define B_    64
#define T_    2048
#define H_    512
#define G_    2048      // 4*H
#define NCTA  128       // 4 groups x 32 CTAs
#define GCTA  32        // CTAs per group
#define GB    16        // batches per group
#define LC    64        // gate cols per CTA (16 hcols x 4 gates), j-major: lc = j*4 + gate

// ---------------- device scratch (static, allowed) ----------------
__device__ __align__(16) float  g_hs[(size_t)T_ * H_ * B_];        // 256 MB [t][k][b] natural
__device__ __align__(16) float  g_whP[GCTA * H_ * LC];             // 4 MB [ci][k][lc] j-major
__device__ __align__(16) float  g_bossT4[50 * H_ * 4];             // [v][hcol][gate]
__device__ __align__(16) float  g_heroT4[200 * H_ * 4];            // [v][hcol][gate]
__device__ __align__(16) float4 g_cwb[G_];                         // (Wc0,Wc1,Wc2,bias) by o
__device__ __align__(16) float  g_hbufG[4 * 2 * H_ * GB];          // per-group double-buffered h
__device__ unsigned g_barG[4 * 32];                                // per-group counters, 128B apart

// ---------------- helpers ----------------
__device__ __forceinline__ ull pk2(float x, float y) {
    ull r; asm("mov.b64 %0, {%1,%2};" : "=l"(r) : "f"(x), "f"(y)); return r;
}
__device__ __forceinline__ float2 upk(ull v) {
    float2 f; asm("mov.b64 {%0,%1}, %2;" : "=f"(f.x), "=f"(f.y) : "l"(v)); return f;
}
__device__ __forceinline__ void fma2(ull& d, ull a, ull b) {
    asm("fma.rn.f32x2 %0, %1, %2, %3;" : "=l"(d) : "l"(a), "l"(b), "l"(d));
}
__device__ __forceinline__ void cp16(uint32_t s, const void* g) {
    asm volatile("cp.async.cg.shared.global [%0], [%1], 16;" :: "r"(s), "l"(g) : "memory");
}
__device__ __forceinline__ void cpcommit() { asm volatile("cp.async.commit_group;" ::: "memory"); }
template <int N> __device__ __forceinline__ void cpwait() {
    asm volatile("cp.async.wait_group %0;" :: "n"(N) : "memory");
}
__device__ __forceinline__ float sigf(float x) { return 1.0f / (1.0f + __expf(-x)); }
__device__ __forceinline__ float tanha(float x) {
    float r; asm("tanh.approx.f32 %0, %1;" : "=f"(r) : "f"(x)); return r;
}

// ---------------- kernel 0: init ----------------
__global__ void k_init() {
    int tid = threadIdx.x + blockIdx.x * blockDim.x;
    if (tid < 4 * 32) g_barG[tid] = 0u;
    for (int i = tid; i < 4 * 2 * H_ * GB; i += blockDim.x * gridDim.x)
        g_hbufG[i] = 0.f;
}

// ---------------- kernel 1: projections (gate-packed tables) ----------------
__global__ void k_prep(const float* __restrict__ boss_table,
                       const float* __restrict__ hero_table,
                       const float* __restrict__ W_i,
                       const float* __restrict__ b_lstm) {
    int o = blockIdx.x;
    int gate = o >> 9, hcol = o & 511;
    int tid = threadIdx.x;
    if (tid < 50) {
        float s = 0.f;
        #pragma unroll
        for (int e = 0; e < 32; ++e) s += boss_table[tid * 32 + e] * W_i[e * G_ + o];
        g_bossT4[(tid * H_ + hcol) * 4 + gate] = s;
    } else if (tid < 250) {
        int v = tid - 50;
        float s = 0.f;
        #pragma unroll
        for (int e = 0; e < 32; ++e) s += hero_table[v * 32 + e] * W_i[(32 + e) * G_ + o];
        g_heroT4[(v * H_ + hcol) * 4 + gate] = s;
    } else if (tid == 250) {
        g_cwb[o] = make_float4(W_i[64 * G_ + o], W_i[65 * G_ + o], W_i[66 * G_ + o], b_lstm[o]);
    }
}

// ---------------- kernel 1b: W_h permute -> whP[ci][k][lc] (j-major lc) -------
__global__ void k_prepW(const float* __restrict__ W_h) {
    int ci = blockIdx.x >> 4, kb = blockIdx.x & 15;
    int tid = threadIdx.x;
    int k = kb * 32 + (tid >> 3);
    int lc0 = (tid & 7) * 8;
    #pragma unroll
    for (int l = 0; l < 8; ++l) {
        int lc = lc0 + l;
        int gate = lc & 3, j = lc >> 2;        // j-major: lc = j*4 + gate
        int o = gate * H_ + ci * 16 + j;
        g_whP[((size_t)ci * H_ + k) * LC + lc] = W_h[(size_t)k * G_ + o];
    }
}

// ---------------- kernel 3: persistent LSTM recurrence ----------------
#define SM_W    0
#define SM_H    131072
#define SM_P    (131072 + 32768)
#define PS_     4352            // partial stride per warp: 16 rows x 272B
#define SM_STG  (SM_P + 8 * PS_)
#define SMTOT   (SM_STG + 1024)
__global__ void __launch_bounds__(256, 1) k_recur(const int* __restrict__ boss_anim,
                                                  const int* __restrict__ hero_anim,
                                                  const float* __restrict__ cont) {
    extern __shared__ char smem[];
    char* whsB = smem + SM_W;           // [512][256B]
    char* hsmB = smem + SM_H;           // [512][64B]
    char* part = smem + SM_P;           // [8][16][272B]
    int*   ibuf = (int*)(smem + SM_STG);           // [2][16][2]
    float* cbuf = (float*)(smem + SM_STG + 256);   // [2][16][4]

    int cta = blockIdx.x, tid = threadIdx.x;
    int w = tid >> 5, lane = tid & 31;
    int cg = lane & 7, bg = lane >> 3;  // 8 col-groups x 4 batch-groups
    int gp = cta >> 5, ci = cta & 31;

    // one-time: stage W slice
    {
        const float4* wsrc = (const float4*)(g_whP + (size_t)ci * H_ * LC);
        float4* wdst = (float4*)whsB;
        for (int i = tid; i < H_ * LC / 4; i += 256) wdst[i] = wsrc[i];
    }

    // reduce/gate roles: thread = (j in 16 h-cols, b2 in 16 batches)
    int j = tid >> 4, b2 = tid & 15;
    int hcol = ci * 16 + j;
    float c_state = 0.f;

    // preload cont-weights+bias for this thread's 4 gate cols
    float4 cw[4];
    #pragma unroll
    for (int g = 0; g < 4; ++g) cw[g] = g_cwb[g * H_ + hcol];

    uint32_t hsm_s = (uint32_t)__cvta_generic_to_shared(hsmB);
    float* hbuf0 = g_hbufG + (size_t)gp * 2 * H_ * GB;
    unsigned* bar = g_barG + gp * 32;

    // ---- prologue: stage slot 0 + compute xg(t=0) ----
    if (w == 0) {
        if (lane < 16) {
            int b = gp * GB + lane;
            int bi = boss_anim[b * T_ + 0]; bi = min(max(bi, 0), 49);
            ibuf[(0 * 16 + lane) * 2 + 0] = bi;
            size_t cb = (size_t)b * T_ * 3;
            cbuf[(0 * 16 + lane) * 4 + 0] = cont[cb + 0];
            cbuf[(0 * 16 + lane) * 4 + 1] = cont[cb + 1];
            cbuf[(0 * 16 + lane) * 4 + 2] = cont[cb + 2];
        } else {
            int bb = lane - 16;
            int b = gp * GB + bb;
            int hi = hero_anim[b * T_ + 0]; hi = min(max(hi, 0), 199);
            ibuf[(0 * 16 + bb) * 2 + 1] = hi;
        }
    }
    __syncthreads();

    float xcur[4];
    {
        int bi = ibuf[(0 * 16 + b2) * 2 + 0];
        int hi = ibuf[(0 * 16 + b2) * 2 + 1];
        float c0 = cbuf[(0 * 16 + b2) * 4 + 0];
        float c1 = cbuf[(0 * 16 + b2) * 4 + 1];
        float c2 = cbuf[(0 * 16 + b2) * 4 + 2];
        float4 bv4 = *(const float4*)(g_bossT4 + ((size_t)bi * H_ + hcol) * 4);
        float4 hv4 = *(const float4*)(g_heroT4 + ((size_t)hi * H_ + hcol) * 4);
        xcur[0] = bv4.x + hv4.x + c0 * cw[0].x + c1 * cw[0].y + c2 * cw[0].z + cw[0].w;
        xcur[1] = bv4.y + hv4.y + c0 * cw[1].x + c1 * cw[1].y + c2 * cw[1].z + cw[1].w;
        xcur[2] = bv4.z + hv4.z + c0 * cw[2].x + c1 * cw[2].y + c2 * cw[2].z + cw[2].w;
        xcur[3] = bv4.w + hv4.w + c0 * cw[3].x + c1 * cw[3].y + c2 * cw[3].z + cw[3].w;
    }

    for (int t = 0; t < T_; ++t) {
        int tp = min(t + 1, T_ - 1);
        int nb = (t + 1) & 1;

        // -------- async-load own 4KB k-slice FIRST (4 groups of 2 cp16) --------
        const char* src = (const char*)(hbuf0 + (size_t)(t & 1) * H_ * GB) + w * 4096;
        uint32_t dst = hsm_s + w * 4096;
        #pragma unroll
        for (int g = 0; g < 4; ++g) {
            cp16(dst + (g * 2 + 0) * 512 + lane * 16, src + (g * 2 + 0) * 512 + lane * 16);
            cp16(dst + (g * 2 + 1) * 512 + lane * 16, src + (g * 2 + 1) * 512 + lane * 16);
            cpcommit();
        }

        // -------- warp0: issue stage loads for t+1 (into regs) --------
        int sbi = 0, shi = 0; float sc0 = 0, sc1 = 0, sc2 = 0;
        if (w == 0) {
            if (lane < 16) {
                int b = gp * GB + lane;
                sbi = boss_anim[b * T_ + tp];
                size_t cb = ((size_t)b * T_ + tp) * 3;
                sc0 = cont[cb + 0]; sc1 = cont[cb + 1]; sc2 = cont[cb + 2];
            } else {
                int b = gp * GB + (lane - 16);
                shi = hero_anim[b * T_ + tp];
            }
        }

        ull acc[16];
        #pragma unroll
        for (int a = 0; a < 16; ++a) acc[a] = 0ull;

        const char* wP = whsB + (w * 64) * 256 + cg * 16;
        const char* hP = hsmB + (w * 64) * 64 + bg * 16;

        #define GBODY                                                          \
        {                                                                      \
            float4 hv = *(const float4*)(hP);                                  \
            ulonglong2 wA = *(const ulonglong2*)(wP);                          \
            ulonglong2 wB = *(const ulonglong2*)(wP + 128);                    \
            ull h0 = pk2(hv.x, hv.x), h1 = pk2(hv.y, hv.y);                    \
            ull h2 = pk2(hv.z, hv.z), h3 = pk2(hv.w, hv.w);                    \
            fma2(acc[0],  wA.x, h0); fma2(acc[1],  wA.x, h1);                  \
            fma2(acc[2],  wA.x, h2); fma2(acc[3],  wA.x, h3);                  \
            fma2(acc[4],  wA.y, h0); fma2(acc[5],  wA.y, h1);                  \
            fma2(acc[6],  wA.y, h2); fma2(acc[7],  wA.y, h3);                  \
            fma2(acc[8],  wB.x, h0); fma2(acc[9],  wB.x, h1);                  \
            fma2(acc[10], wB.x, h2); fma2(acc[11], wB.x, h3);                  \
            fma2(acc[12], wB.y, h0); fma2(acc[13], wB.y, h1);                  \
            fma2(acc[14], wB.y, h2); fma2(acc[15], wB.y, h3);                  \
            wP += 256; hP += 64;                                               \
        }

        // -------- GEMM: 4 chunks of 16 k, each gated by its cp group --------
        cpwait<3>();
        __syncwarp();
        #pragma unroll 8
        for (int k = 0; k < 16; ++k) GBODY
        cpwait<2>();
        __syncwarp();
        #pragma unroll 8
        for (int k = 0; k < 16; ++k) GBODY
        cpwait<1>();
        __syncwarp();
        #pragma unroll 8
        for (int k = 0; k < 16; ++k) GBODY
        cpwait<0>();
        __syncwarp();
        #pragma unroll 8
        for (int k = 0; k < 16; ++k) GBODY
        #undef GBODY

        // -------- warp0: commit stage to smem (before the block sync) --------
        if (w == 0) {
            if (lane < 16) {
                int bi = min(max(sbi, 0), 49);
                ibuf[(nb * 16 + lane) * 2 + 0] = bi;
                cbuf[(nb * 16 + lane) * 4 + 0] = sc0;
                cbuf[(nb * 16 + lane) * 4 + 1] = sc1;
                cbuf[(nb * 16 + lane) * 4 + 2] = sc2;
            } else {
                int hi = min(max(shi, 0), 199);
                ibuf[(nb * 16 + (lane - 16)) * 2 + 1] = hi;
            }
        }

        // -------- store partials [w][b2 (pad 272B)][lc] --------
        #pragma unroll
        for (int b = 0; b < 4; ++b) {
            char* pb = part + w * PS_ + (bg * 4 + b) * 272 + cg * 16;
            *(ulonglong2*)(pb)       = make_ulonglong2(acc[0 + b], acc[4 + b]);
            *(ulonglong2*)(pb + 128) = make_ulonglong2(acc[8 + b], acc[12 + b]);
        }
        __syncthreads();

        // -------- issue gather LDGs for xg(t+1) --------
        int nbi = ibuf[(nb * 16 + b2) * 2 + 0];
        int nhi = ibuf[(nb * 16 + b2) * 2 + 1];
        float nc0 = cbuf[(nb * 16 + b2) * 4 + 0];
        float nc1 = cbuf[(nb * 16 + b2) * 4 + 1];
        float nc2 = cbuf[(nb * 16 + b2) * 4 + 2];
        float4 bv4 = *(const float4*)(g_bossT4 + ((size_t)nbi * H_ + hcol) * 4);
        float4 hv4 = *(const float4*)(g_heroT4 + ((size_t)nhi * H_ + hcol) * 4);

        // -------- fused ksplit reduction + gates (VECTORIZED: lc j-major) ------
        // thread (j, b2) reads its 4 gate partials as one float4 per warp-slice
        float gs0 = 0.f, gs1 = 0.f, gs2 = 0.f, gs3 = 0.f;
        #pragma unroll
        for (int w8 = 0; w8 < 8; ++w8) {
            float4 p = *(const float4*)(part + w8 * PS_ + b2 * 272 + j * 16);
            gs0 += p.x; gs1 += p.y; gs2 += p.z; gs3 += p.w;
        }
        float gi = gs0 + xcur[0], gf = gs1 + xcur[1];
        float gg = gs2 + xcur[2], go = gs3 + xcur[3];
        float iv = sigf(gi), fv = sigf(gf), gv = tanha(gg), ov = sigf(go);
        c_state = fv * c_state + iv * gv;
        float h = ov * tanha(c_state);
        hbuf0[(size_t)nb * H_ * GB + hcol * GB + b2] = h;

        // -------- compute xg(t+1) --------
        xcur[0] = bv4.x + hv4.x + nc0 * cw[0].x + nc1 * cw[0].y + nc2 * cw[0].z + cw[0].w;
        xcur[1] = bv4.y + hv4.y + nc0 * cw[1].x + nc1 * cw[1].y + nc2 * cw[1].z + cw[1].w;
        xcur[2] = bv4.z + hv4.z + nc0 * cw[2].x + nc1 * cw[2].y + nc2 * cw[2].z + cw[2].w;
        xcur[3] = bv4.w + hv4.w + nc0 * cw[3].x + nc1 * cw[3].y + nc2 * cw[3].z + cw[3].w;

        // -------- group barrier (frozen R7 form) with archive store
        //          overlapped into the spin window --------
        __threadfence();
        __syncthreads();
        g_hs[((size_t)t * H_ + hcol) * B_ + gp * GB + b2] = h;   // off the drain path
        if (tid == 0) {
            atomicAdd(bar, 1u);
            unsigned tgt = (unsigned)GCTA * (unsigned)(t + 1);
            while (*(volatile unsigned*)bar < tgt) { }
            __threadfence();
        }
        __syncthreads();
    }
}

// ---------------- kernel 4: MLP epilogue ----------------
__global__ void __launch_bounds__(256, 1) k_mlp(const float* __restrict__ W1,
                                                const float* __restrict__ b1,
                                                const float* __restrict__ W2,
                                                const float* __restrict__ b2,
                                                float* __restrict__ out) {
    extern __shared__ char smem[];
    float* hsm = (float*)smem;                          // [512][64] 128KB
    float* w1c = (float*)(smem + 131072);               // [64][256] 64KB
    float* b1s = (float*)(smem + 131072 + 65536);       // 256
    float* w2s = b1s + 256;                             // 256
    float* red = w2s + 256;                             // [16][64]

    int t = blockIdx.x, tid = threadIdx.x;

    const float4* hsrc = (const float4*)(g_hs + (size_t)t * (H_ * B_));
    float4* hd = (float4*)hsm;
    for (int i = tid; i < H_ * B_ / 4; i += 256) hd[i] = hsrc[i];
    b1s[tid] = b1[tid];
    w2s[tid] = W2[tid];
    __syncthreads();

    int bt = tid & 15, mt = tid >> 4;
    int b0 = bt * 4, m0 = mt * 16;

    ull acc[16][2];
    #pragma unroll
    for (int m = 0; m < 16; ++m) {
        float bv = b1s[m0 + m];
        acc[m][0] = pk2(bv, bv);
        acc[m][1] = pk2(bv, bv);
    }

    for (int kc = 0; kc < 8; ++kc) {
        if (kc > 0) __syncthreads();
        const float4* wsrc = (const float4*)(W1 + (size_t)kc * 64 * 256);
        for (int i = tid; i < 4096; i += 256) ((float4*)w1c)[i] = wsrc[i];
        __syncthreads();
        #pragma unroll 4
        for (int k = 0; k < 64; ++k) {
            const ull* hp = (const ull*)&hsm[(kc * 64 + k) * B_ + b0];
            ull h01 = hp[0], h23 = hp[1];
            const float* wr = &w1c[k * 256 + m0];
            #pragma unroll
            for (int m4 = 0; m4 < 4; ++m4) {
                float4 wv = *(const float4*)&wr[m4 * 4];
                ull wa = pk2(wv.x, wv.x), wb = pk2(wv.y, wv.y);
                ull wc = pk2(wv.z, wv.z), wd = pk2(wv.w, wv.w);
                fma2(acc[m4 * 4 + 0][0], h01, wa); fma2(acc[m4 * 4 + 0][1], h23, wa);
                fma2(acc[m4 * 4 + 1][0], h01, wb); fma2(acc[m4 * 4 + 1][1], h23, wb);
                fma2(acc[m4 * 4 + 2][0], h01, wc); fma2(acc[m4 * 4 + 2][1], h23, wc);
                fma2(acc[m4 * 4 + 3][0], h01, wd); fma2(acc[m4 * 4 + 3][1], h23, wd);
            }
        }
    }

    float p0 = 0.f, p1 = 0.f, p2 = 0.f, p3 = 0.f;
    #pragma unroll
    for (int m = 0; m < 16; ++m) {
        float2 v0 = upk(acc[m][0]), v1 = upk(acc[m][1]);
        float wv = w2s[m0 + m];
        p0 += fmaxf(v0.x, 0.f) * wv;
        p1 += fmaxf(v0.y, 0.f) * wv;
        p2 += fmaxf(v1.x, 0.f) * wv;
        p3 += fmaxf(v1.y, 0.f) * wv;
    }
    red[mt * B_ + b0 + 0] = p0;
    red[mt * B_ + b0 + 1] = p1;
    red[mt * B_ + b0 + 2] = p2;
    red[mt * B_ + b0 + 3] = p3;
    __syncthreads();
    if (tid < B_) {
        float s = b2[0];
        #pragma unroll
        for (int q = 0; q < 16; ++q) s += red[q * B_ + tid];
        out[(size_t)tid * T_ + t] = s;
    }
}

// ---------------- launch ----------------
extern "C" void kernel_launch(void* const* d_in, const int* in_sizes, int n_in,
                              void* d_out, int out_size) {
    const int*   boss_anim  = (const int*)d_in[0];
    const int*   hero_anim  = (const int*)d_in[1];
    const float* continuous = (const float*)d_in[2];
    const float* boss_table = (const float*)d_in[3];
    const float* hero_table = (const float*)d_in[4];
    const float* W_i        = (const float*)d_in[5];
    const float* W_h        = (const float*)d_in[6];
    const float* b_lstm     = (const float*)d_in[7];
    const float* W1         = (const float*)d_in[8];
    const float* b1         = (const float*)d_in[9];
    const float* W2         = (const float*)d_in[10];
    const float* b2         = (const float*)d_in[11];
    float* out = (float*)d_out;

    static bool attr_done = false;
    if (!attr_done) {
        cudaFuncSetAttribute(k_recur, cudaFuncAttributeMaxDynamicSharedMemorySize, SMTOT);
        cudaFuncSetAttribute(k_mlp,   cudaFuncAttributeMaxDynamicSharedMemorySize, 131072 + 65536 + 2048 + 4096);
        attr_done = true;
    }

    k_init<<<32, 256>>>();
    k_prep<<<G_, 256>>>(boss_table, hero_table, W_i, b_lstm);
    k_prepW<<<512, 256>>>(W_h);
    k_recur<<<NCTA, 256, SMTOT>>>(boss_anim, hero_anim, continuous);
    k_mlp<<<T_, 256, 131072 + 65536 + 2048 + 4096>>>(W1, b1, W2, b2, out);
}

// round 17
// speedup vs baseline: 1.3541x; 1.2294x over previous
#include <cuda_runtime.h>
#include <cuda_bf16.h>
#include <cstdint>

typedef unsigned long long ull;

#define B_    64
#define T_    2048
#define H_    512
#define G_    2048      // 4*H
#define NCTA  128       // 4 groups x 32 CTAs
#define GCTA  32        // CTAs per group
#define GB    16        // batches per group
#define LC    64        // gate cols per CTA, j-major: lc = j*4 + gate

// ---------------- layout constants ----------------
#define WROW   1040                  // W tile row stride (bytes), 520 bf16 cols
#define WTILE  (64 * WROW)           // 66560 per hi/lo
#define HROW   48                    // h tile row stride (bytes), 24 bf16 cols
#define HTILE  (512 * HROW)          // 24576 per hi/lo
#define HBUF   (2 * HTILE)           // 49152 per buffer (hi+lo)

// ---------------- device scratch (static, allowed) ----------------
__device__ __align__(16) float   g_hs[(size_t)T_ * H_ * B_];    // 256 MB [t][k][b]
__device__ __align__(16) uint8_t g_wT[GCTA][2 * WTILE];         // W: hi @0, lo @WTILE
__device__ __align__(16) uint8_t g_hT[4][2][HBUF];              // h: hi @0, lo @HTILE
__device__ __align__(16) float   g_bossT4[50 * H_ * 4];         // [v][hcol][gate]
__device__ __align__(16) float   g_heroT4[200 * H_ * 4];        // [v][hcol][gate]
__device__ __align__(16) float4  g_cwb[G_];                     // (Wc0,Wc1,Wc2,bias) by o
__device__ unsigned g_barG[4 * 32];                             // per-group counters

// ---------------- helpers ----------------
__device__ __forceinline__ ull pk2(float x, float y) {
    ull r; asm("mov.b64 %0, {%1,%2};" : "=l"(r) : "f"(x), "f"(y)); return r;
}
__device__ __forceinline__ float2 upk(ull v) {
    float2 f; asm("mov.b64 {%0,%1}, %2;" : "=f"(f.x), "=f"(f.y) : "l"(v)); return f;
}
__device__ __forceinline__ void fma2(ull& d, ull a, ull b) {
    asm("fma.rn.f32x2 %0, %1, %2, %3;" : "=l"(d) : "l"(a), "l"(b), "l"(d));
}
__device__ __forceinline__ void cp16(uint32_t s, const void* g) {
    asm volatile("cp.async.cg.shared.global [%0], [%1], 16;" :: "r"(s), "l"(g) : "memory");
}
__device__ __forceinline__ void cpcommit() { asm volatile("cp.async.commit_group;" ::: "memory"); }
template <int N> __device__ __forceinline__ void cpwait() {
    asm volatile("cp.async.wait_group %0;" :: "n"(N) : "memory");
}
__device__ __forceinline__ float sigf(float x) { return 1.0f / (1.0f + __expf(-x)); }
__device__ __forceinline__ float tanha(float x) {
    float r; asm("tanh.approx.f32 %0, %1;" : "=f"(r) : "f"(x)); return r;
}

// ldmatrix / mma wrappers (generic PTX, legal on compute_103)
__device__ __forceinline__ void ldsm_x4(uint32_t& r0, uint32_t& r1, uint32_t& r2, uint32_t& r3,
                                        uint32_t addr) {
    asm volatile("ldmatrix.sync.aligned.m8n8.x4.shared.b16 {%0,%1,%2,%3}, [%4];"
                 : "=r"(r0), "=r"(r1), "=r"(r2), "=r"(r3) : "r"(addr));
}
__device__ __forceinline__ void ldsm_x2t(uint32_t& r0, uint32_t& r1, uint32_t addr) {
    asm volatile("ldmatrix.sync.aligned.m8n8.x2.trans.shared.b16 {%0,%1}, [%2];"
                 : "=r"(r0), "=r"(r1) : "r"(addr));
}
__device__ __forceinline__ void mma16816(float* c, const uint32_t* a, const uint32_t* b) {
    asm volatile("mma.sync.aligned.m16n8k16.row.col.f32.bf16.bf16.f32 "
                 "{%0,%1,%2,%3}, {%4,%5,%6,%7}, {%8,%9}, {%0,%1,%2,%3};"
                 : "+f"(c[0]), "+f"(c[1]), "+f"(c[2]), "+f"(c[3])
                 : "r"(a[0]), "r"(a[1]), "r"(a[2]), "r"(a[3]), "r"(b[0]), "r"(b[1]));
}

// ---------------- kernel 0: init ----------------
__global__ void k_init() {
    int tid = threadIdx.x + blockIdx.x * blockDim.x;
    int stride = blockDim.x * gridDim.x;
    if (tid < 4 * 32) g_barG[tid] = 0u;
    uint32_t* ht = (uint32_t*)g_hT;
    for (size_t i = tid; i < sizeof(g_hT) / 4; i += stride) ht[i] = 0u;
}

// ---------------- kernel 1: projections (gate-packed tables) ----------------
__global__ void k_prep(const float* __restrict__ boss_table,
                       const float* __restrict__ hero_table,
                       const float* __restrict__ W_i,
                       const float* __restrict__ b_lstm) {
    int o = blockIdx.x;
    int gate = o >> 9, hcol = o & 511;
    int tid = threadIdx.x;
    if (tid < 50) {
        float s = 0.f;
        #pragma unroll
        for (int e = 0; e < 32; ++e) s += boss_table[tid * 32 + e] * W_i[e * G_ + o];
        g_bossT4[(tid * H_ + hcol) * 4 + gate] = s;
    } else if (tid < 250) {
        int v = tid - 50;
        float s = 0.f;
        #pragma unroll
        for (int e = 0; e < 32; ++e) s += hero_table[v * 32 + e] * W_i[(32 + e) * G_ + o];
        g_heroT4[(v * H_ + hcol) * 4 + gate] = s;
    } else if (tid == 250) {
        g_cwb[o] = make_float4(W_i[64 * G_ + o], W_i[65 * G_ + o], W_i[66 * G_ + o], b_lstm[o]);
    }
}

// ---------------- kernel 1b: W_h -> bf16 hi/lo tiles [lc][k] (padded rows) ------
__global__ void k_prepW(const float* __restrict__ W_h) {
    int ci = blockIdx.x >> 4, kb = blockIdx.x & 15;
    int tid = threadIdx.x;
    int k = kb * 32 + (tid >> 3);
    int lc0 = (tid & 7) * 8;
    uint8_t* base = g_wT[ci];
    #pragma unroll
    for (int l = 0; l < 8; ++l) {
        int lc = lc0 + l;
        int gate = lc & 3, j = lc >> 2;     // j-major: lc = j*4 + gate
        int o = gate * H_ + ci * 16 + j;
        float wv = W_h[(size_t)k * G_ + o];
        __nv_bfloat16 hi = __float2bfloat16_rn(wv);
        __nv_bfloat16 lo = __float2bfloat16_rn(wv - __bfloat162float(hi));
        uint32_t off = (uint32_t)lc * WROW + (uint32_t)k * 2;
        *(__nv_bfloat16*)(base + off) = hi;
        *(__nv_bfloat16*)(base + WTILE + off) = lo;
    }
}

// ---------------- kernel 3: persistent LSTM recurrence (mma.sync GEMM) ----------
// smem: Whi|Wlo 133120 | Bhi|Blo 49152 | gsm 4352 | ibuf 256 | cbuf 512
#define SM_W    0
#define SM_B    133120
#define SM_GS   (133120 + 49152)
#define SM_IBUF (SM_GS + 4352)
#define SM_CBUF (SM_IBUF + 256)
#define SMTOT   (SM_CBUF + 512)
__global__ void __launch_bounds__(256, 1) k_recur(const int* __restrict__ boss_anim,
                                                  const int* __restrict__ hero_anim,
                                                  const float* __restrict__ cont) {
    extern __shared__ char smem[];
    int*   ibuf = (int*)(smem + SM_IBUF);          // [2][16][2] = 256B
    float* cbuf = (float*)(smem + SM_CBUF);        // [2][16][4] = 512B
    float* gsf  = (float*)(smem + SM_GS);          // [16 b][68 pad] floats

    int cta = blockIdx.x, tid = threadIdx.x;
    int w = tid >> 5, lane = tid & 31;
    int gp = cta >> 5, ci = cta & 31;

    uint32_t sb;
    asm("{ .reg .u64 t; cvta.to.shared.u64 t, %1; cvt.u32.u64 %0, t; }" : "=r"(sb) : "l"(smem));

    // one-time: stage W tiles (133120B, linear copy)
    {
        const float4* src = (const float4*)g_wT[ci];
        float4* dst = (float4*)smem;
        for (int i = tid; i < 2 * WTILE / 16; i += 256) dst[i] = src[i];
    }

    // MMA roles
    int m0 = (w & 3) * 16;              // lc tile
    int n0 = (w >> 2) * 8;              // b tile
    int arow = m0 + (lane & 7) + ((lane >> 3) & 1) * 8;
    int akof = ((lane >> 4) & 1) * 8;
    uint32_t aAhi = sb + SM_W + (uint32_t)arow * WROW + (uint32_t)akof * 2;
    uint32_t aAlo = aAhi + WTILE;
    uint32_t aBhi = sb + SM_B + (uint32_t)(lane & 15) * HROW + (uint32_t)n0 * 2;
    uint32_t aBlo = aBhi + HTILE;

    // gate roles: thread = (j in 16 h-cols, b2 in 16 batches)
    int j = tid >> 4, b2 = tid & 15;
    int hcol = ci * 16 + j;
    float c_state = 0.f;

    float4 cw[4];
    #pragma unroll
    for (int g = 0; g < 4; ++g) cw[g] = g_cwb[g * H_ + hcol];

    unsigned* bar = g_barG + gp * 32;

    // ---- prologue: stage slot 0 + compute xg(t=0) ----
    if (w == 0) {
        if (lane < 16) {
            int b = gp * GB + lane;
            int bi = boss_anim[b * T_ + 0]; bi = min(max(bi, 0), 49);
            ibuf[(0 * 16 + lane) * 2 + 0] = bi;
            size_t cb = (size_t)b * T_ * 3;
            cbuf[(0 * 16 + lane) * 4 + 0] = cont[cb + 0];
            cbuf[(0 * 16 + lane) * 4 + 1] = cont[cb + 1];
            cbuf[(0 * 16 + lane) * 4 + 2] = cont[cb + 2];
        } else {
            int bb = lane - 16;
            int b = gp * GB + bb;
            int hi = hero_anim[b * T_ + 0]; hi = min(max(hi, 0), 199);
            ibuf[(0 * 16 + bb) * 2 + 1] = hi;
        }
    }
    __syncthreads();

    float xcur[4];
    {
        int bi = ibuf[(0 * 16 + b2) * 2 + 0];
        int hi = ibuf[(0 * 16 + b2) * 2 + 1];
        float c0 = cbuf[(0 * 16 + b2) * 4 + 0];
        float c1 = cbuf[(0 * 16 + b2) * 4 + 1];
        float c2 = cbuf[(0 * 16 + b2) * 4 + 2];
        float4 bv4 = *(const float4*)(g_bossT4 + ((size_t)bi * H_ + hcol) * 4);
        float4 hv4 = *(const float4*)(g_heroT4 + ((size_t)hi * H_ + hcol) * 4);
        xcur[0] = bv4.x + hv4.x + c0 * cw[0].x + c1 * cw[0].y + c2 * cw[0].z + cw[0].w;
        xcur[1] = bv4.y + hv4.y + c0 * cw[1].x + c1 * cw[1].y + c2 * cw[1].z + cw[1].w;
        xcur[2] = bv4.z + hv4.z + c0 * cw[2].x + c1 * cw[2].y + c2 * cw[2].z + cw[2].w;
        xcur[3] = bv4.w + hv4.w + c0 * cw[3].x + c1 * cw[3].y + c2 * cw[3].z + cw[3].w;
    }

    for (int t = 0; t < T_; ++t) {
        int tp = min(t + 1, T_ - 1);
        int nb = (t + 1) & 1;

        // -------- cp.async h tiles (49152B flat = 3072 cp16, 12/thread) --------
        {
            const char* src = (const char*)g_hT[gp][t & 1];
            uint32_t dst = sb + SM_B;
            #pragma unroll
            for (int i = 0; i < 12; ++i) {
                int e = tid + i * 256;
                cp16(dst + e * 16, src + e * 16);
            }
            cpcommit();
        }

        // -------- warp0: issue stage loads for t+1 (into regs) --------
        int sbi = 0, shi = 0; float sc0 = 0, sc1 = 0, sc2 = 0;
        if (w == 0) {
            if (lane < 16) {
                int b = gp * GB + lane;
                sbi = boss_anim[b * T_ + tp];
                size_t cb = ((size_t)b * T_ + tp) * 3;
                sc0 = cont[cb + 0]; sc1 = cont[cb + 1]; sc2 = cont[cb + 2];
            } else {
                int b = gp * GB + (lane - 16);
                shi = hero_anim[b * T_ + tp];
            }
        }

        cpwait<0>();
        __syncthreads();

        // -------- tensor-core GEMM: C[m16][n8] over k=512 --------
        float Ca[4] = {0, 0, 0, 0};   // Whi x hhi
        float Cb[4] = {0, 0, 0, 0};   // Whi x hlo
        float Cc[4] = {0, 0, 0, 0};   // Wlo x hhi
        {
            uint32_t pAhi = aAhi, pAlo = aAlo, pBhi = aBhi, pBlo = aBlo;
            #pragma unroll 4
            for (int ks = 0; ks < 32; ++ks) {
                uint32_t ah[4], al[4], bh[2], bl[2];
                ldsm_x4(ah[0], ah[1], ah[2], ah[3], pAhi);
                ldsm_x2t(bh[0], bh[1], pBhi);
                ldsm_x4(al[0], al[1], al[2], al[3], pAlo);
                ldsm_x2t(bl[0], bl[1], pBlo);
                mma16816(Ca, ah, bh);
                mma16816(Cb, ah, bl);
                mma16816(Cc, al, bh);
                pAhi += 32; pAlo += 32;          // +16 k * 2B
                pBhi += 16 * HROW; pBlo += 16 * HROW;
            }
        }

        // -------- warp0: commit stage to smem (read after next block sync) ----
        if (w == 0) {
            if (lane < 16) {
                int bi = min(max(sbi, 0), 49);
                ibuf[(nb * 16 + lane) * 2 + 0] = bi;
                cbuf[(nb * 16 + lane) * 4 + 0] = sc0;
                cbuf[(nb * 16 + lane) * 4 + 1] = sc1;
                cbuf[(nb * 16 + lane) * 4 + 2] = sc2;
            } else {
                int hi = min(max(shi, 0), 199);
                ibuf[(nb * 16 + (lane - 16)) * 2 + 1] = hi;
            }
        }

        // -------- epilogue: C -> gsm[b][lc] (pad 68 floats/row) --------
        {
            int row0 = m0 + (lane >> 2);
            int col0 = n0 + 2 * (lane & 3);
            float s0 = Ca[0] + Cb[0] + Cc[0];
            float s1 = Ca[1] + Cb[1] + Cc[1];
            float s2 = Ca[2] + Cb[2] + Cc[2];
            float s3 = Ca[3] + Cb[3] + Cc[3];
            gsf[col0 * 68 + row0]           = s0;
            gsf[(col0 + 1) * 68 + row0]     = s1;
            gsf[col0 * 68 + row0 + 8]       = s2;
            gsf[(col0 + 1) * 68 + row0 + 8] = s3;
        }
        __syncthreads();

        // -------- gates (thread = (j, b2)); lc j-major => float4 read --------
        float4 gv = *(const float4*)(gsf + b2 * 68 + j * 4);
        float gi = gv.x + xcur[0], gf = gv.y + xcur[1];
        float gg = gv.z + xcur[2], go = gv.w + xcur[3];
        float iv = sigf(gi), fv = sigf(gf), gvv = tanha(gg), ov = sigf(go);
        c_state = fv * c_state + iv * gvv;
        float h = ov * tanha(c_state);

        // store h as bf16 hi/lo into next tile [k=hcol][b]
        {
            __nv_bfloat16 hh = __float2bfloat16_rn(h);
            __nv_bfloat16 hl = __float2bfloat16_rn(h - __bfloat162float(hh));
            uint8_t* hb = g_hT[gp][nb];
            uint32_t off = (uint32_t)hcol * HROW + (uint32_t)b2 * 2;
            *(__nv_bfloat16*)(hb + off) = hh;
            *(__nv_bfloat16*)(hb + HTILE + off) = hl;
        }

        // -------- compute xg(t+1) --------
        {
            int nbi = ibuf[(nb * 16 + b2) * 2 + 0];
            int nhi = ibuf[(nb * 16 + b2) * 2 + 1];
            float nc0 = cbuf[(nb * 16 + b2) * 4 + 0];
            float nc1 = cbuf[(nb * 16 + b2) * 4 + 1];
            float nc2 = cbuf[(nb * 16 + b2) * 4 + 2];
            float4 bv4 = *(const float4*)(g_bossT4 + ((size_t)nbi * H_ + hcol) * 4);
            float4 hv4 = *(const float4*)(g_heroT4 + ((size_t)nhi * H_ + hcol) * 4);
            xcur[0] = bv4.x + hv4.x + nc0 * cw[0].x + nc1 * cw[0].y + nc2 * cw[0].z + cw[0].w;
            xcur[1] = bv4.y + hv4.y + nc0 * cw[1].x + nc1 * cw[1].y + nc2 * cw[1].z + cw[1].w;
            xcur[2] = bv4.z + hv4.z + nc0 * cw[2].x + nc1 * cw[2].y + nc2 * cw[2].z + cw[2].w;
            xcur[3] = bv4.w + hv4.w + nc0 * cw[3].x + nc1 * cw[3].y + nc2 * cw[3].z + cw[3].w;
        }

        // -------- frozen group barrier, archive store in spin window --------
        __threadfence();
        __syncthreads();
        g_hs[((size_t)t * H_ + hcol) * B_ + gp * GB + b2] = h;
        if (tid == 0) {
            atomicAdd(bar, 1u);
            unsigned tgt = (unsigned)GCTA * (unsigned)(t + 1);
            while (*(volatile unsigned*)bar < tgt) { }
            __threadfence();
        }
        __syncthreads();
    }
}

// ---------------- kernel 4: MLP epilogue ----------------
__global__ void __launch_bounds__(256, 1) k_mlp(const float* __restrict__ W1,
                                                const float* __restrict__ b1,
                                                const float* __restrict__ W2,
                                                const float* __restrict__ b2,
                                                float* __restrict__ out) {
    extern __shared__ char smem[];
    float* hsm = (float*)smem;                          // [512][64] 128KB
    float* w1c = (float*)(smem + 131072);               // [64][256] 64KB
    float* b1s = (float*)(smem + 131072 + 65536);       // 256
    float* w2s = b1s + 256;                             // 256
    float* red = w2s + 256;                             // [16][64]

    int t = blockIdx.x, tid = threadIdx.x;

    const float4* hsrc = (const float4*)(g_hs + (size_t)t * (H_ * B_));
    float4* hd = (float4*)hsm;
    for (int i = tid; i < H_ * B_ / 4; i += 256) hd[i] = hsrc[i];
    b1s[tid] = b1[tid];
    w2s[tid] = W2[tid];
    __syncthreads();

    int bt = tid & 15, mt = tid >> 4;
    int b0 = bt * 4, m0 = mt * 16;

    ull acc[16][2];
    #pragma unroll
    for (int m = 0; m < 16; ++m) {
        float bv = b1s[m0 + m];
        acc[m][0] = pk2(bv, bv);
        acc[m][1] = pk2(bv, bv);
    }

    for (int kc = 0; kc < 8; ++kc) {
        if (kc > 0) __syncthreads();
        const float4* wsrc = (const float4*)(W1 + (size_t)kc * 64 * 256);
        for (int i = tid; i < 4096; i += 256) ((float4*)w1c)[i] = wsrc[i];
        __syncthreads();
        #pragma unroll 4
        for (int k = 0; k < 64; ++k) {
            const ull* hp = (const ull*)&hsm[(kc * 64 + k) * B_ + b0];
            ull h01 = hp[0], h23 = hp[1];
            const float* wr = &w1c[k * 256 + m0];
            #pragma unroll
            for (int m4 = 0; m4 < 4; ++m4) {
                float4 wv = *(const float4*)&wr[m4 * 4];
                ull wa = pk2(wv.x, wv.x), wb = pk2(wv.y, wv.y);
                ull wc = pk2(wv.z, wv.z), wd = pk2(wv.w, wv.w);
                fma2(acc[m4 * 4 + 0][0], h01, wa); fma2(acc[m4 * 4 + 0][1], h23, wa);
                fma2(acc[m4 * 4 + 1][0], h01, wb); fma2(acc[m4 * 4 + 1][1], h23, wb);
                fma2(acc[m4 * 4 + 2][0], h01, wc); fma2(acc[m4 * 4 + 2][1], h23, wc);
                fma2(acc[m4 * 4 + 3][0], h01, wd); fma2(acc[m4 * 4 + 3][1], h23, wd);
            }
        }
    }

    float p0 = 0.f, p1 = 0.f, p2 = 0.f, p3 = 0.f;
    #pragma unroll
    for (int m = 0; m < 16; ++m) {
        float2 v0 = upk(acc[m][0]), v1 = upk(acc[m][1]);
        float wv = w2s[m0 + m];
        p0 += fmaxf(v0.x, 0.f) * wv;
        p1 += fmaxf(v0.y, 0.f) * wv;
        p2 += fmaxf(v1.x, 0.f) * wv;
        p3 += fmaxf(v1.y, 0.f) * wv;
    }
    red[mt * B_ + b0 + 0] = p0;
    red[mt * B_ + b0 + 1] = p1;
    red[mt * B_ + b0 + 2] = p2;
    red[mt * B_ + b0 + 3] = p3;
    __syncthreads();
    if (tid < B_) {
        float s = b2[0];
        #pragma unroll
        for (int q = 0; q < 16; ++q) s += red[q * B_ + tid];
        out[(size_t)tid * T_ + t] = s;
    }
}

// ---------------- launch ----------------
extern "C" void kernel_launch(void* const* d_in, const int* in_sizes, int n_in,
                              void* d_out, int out_size) {
    const int*   boss_anim  = (const int*)d_in[0];
    const int*   hero_anim  = (const int*)d_in[1];
    const float* continuous = (const float*)d_in[2];
    const float* boss_table = (const float*)d_in[3];
    const float* hero_table = (const float*)d_in[4];
    const float* W_i        = (const float*)d_in[5];
    const float* W_h        = (const float*)d_in[6];
    const float* b_lstm     = (const float*)d_in[7];
    const float* W1         = (const float*)d_in[8];
    const float* b1         = (const float*)d_in[9];
    const float* W2         = (const float*)d_in[10];
    const float* b2         = (const float*)d_in[11];
    float* out = (float*)d_out;

    static bool attr_done = false;
    if (!attr_done) {
        cudaFuncSetAttribute(k_recur, cudaFuncAttributeMaxDynamicSharedMemorySize, SMTOT);
        cudaFuncSetAttribute(k_mlp,   cudaFuncAttributeMaxDynamicSharedMemorySize, 131072 + 65536 + 2048 + 4096);
        attr_done = true;
    }

    k_init<<<64, 256>>>();
    k_prep<<<G_, 256>>>(boss_table, hero_table, W_i, b_lstm);
    k_prepW<<<512, 256>>>(W_h);
    k_recur<<<NCTA, 256, SMTOT>>>(boss_anim, hero_anim, continuous);
    k_mlp<<<T_, 256, 131072 + 65536 + 2048 + 4096>>>(W1, b1, W2, b2, out);
}